// round 6
// baseline (speedup 1.0000x reference)
#include <cuda_runtime.h>

#define NT 256

// 8 MB state, tables, composed unitaries — all __device__ globals (no allocs).
__device__ float2 g_psi[16 * 65536];
__device__ float2 g_U[240];       // 60 composed 2x2 unitaries
__device__ float2 g_d0[65536];    // layer0 ring phases, depth 0
__device__ float2 g_d1[65536];    // layer0 ring phases, depth 1
__device__ float2 g_t1[512];      // layer1 ring phases (2 depths x 256)
__device__ float2 g_t2[32];       // layer2 (2 x 16)
__device__ float2 g_t3[8];        // layer3 (2 x 4)

__device__ __forceinline__ float2 cmul(float2 a, float2 b) {
    return make_float2(fmaf(a.x, b.x, -a.y * b.y), fmaf(a.x, b.y, a.y * b.x));
}
__device__ __forceinline__ float2 cadd(float2 a, float2 b) {
    return make_float2(a.x + b.x, a.y + b.y);
}
__device__ __forceinline__ void mm2(const float2* A, const float2* B, float2* C) {
    C[0] = cadd(cmul(A[0], B[0]), cmul(A[1], B[2]));
    C[1] = cadd(cmul(A[0], B[1]), cmul(A[1], B[3]));
    C[2] = cadd(cmul(A[2], B[0]), cmul(A[3], B[2]));
    C[3] = cadd(cmul(A[2], B[1]), cmul(A[3], B[3]));
}

// ---------------------------------------------------------------------------
// Prep: compose RX*RZ*RX unitaries, build all ring-phase tables, zero output.
// Launch: 256 blocks x 256 threads = 65536 threads.
// Wire w lives at amp-index bit (15 - w).
// ---------------------------------------------------------------------------
__global__ __launch_bounds__(NT) void prep_kernel(
    const float* __restrict__ p0, const float* __restrict__ p1,
    const float* __restrict__ p2, const float* __restrict__ p3,
    float* __restrict__ out)
{
    int t = blockIdx.x * blockDim.x + threadIdx.x;   // 0..65535

    // Layer-0 16-wire ring RZZ tables (depths 0 and 1).
    {
        float ph0 = 0.f, ph1 = 0.f;
        #pragma unroll
        for (int j = 0; j < 16; j++) {
            int jn = (j + 1) & 15;
            int x = ((t >> (15 - j)) ^ (t >> (15 - jn))) & 1;
            float sg = x ? 0.5f : -0.5f;
            ph0 += sg * p0[4 * j + 3];
            ph1 += sg * p0[4 * j + 67];
        }
        g_d0[t] = make_float2(cosf(ph0), sinf(ph0));
        g_d1[t] = make_float2(cosf(ph1), sinf(ph1));
    }

    // 60 composed unitaries: U = RX(c) * RZ(b) * RX(a)   (a applied first).
    if (t < 60) {
        const float* pp; int base;
        if (t < 32)      { pp = p0; int d = t >> 4;        int s = t & 15;       base = 4 * s + 64 * d; }
        else if (t < 48) { pp = p1; int d = (t - 32) >> 3; int s = (t - 32) & 7; base = 4 * s + 32 * d; }
        else if (t < 56) { pp = p2; int d = (t - 48) >> 2; int s = (t - 48) & 3; base = 4 * s + 16 * d; }
        else             { pp = p3; int d = (t - 56) >> 1; int s = (t - 56) & 1; base = 4 * s + 8 * d; }
        float a = pp[base] * 0.5f, b = pp[base + 1] * 0.5f, c = pp[base + 2] * 0.5f;
        float ca = cosf(a), sa = sinf(a);
        float cb = cosf(b), sb = sinf(b);
        float cc = cosf(c), sc = sinf(c);
        float2 RXa[4] = { {ca,0.f}, {0.f,-sa}, {0.f,-sa}, {ca,0.f} };
        float2 RZb[4] = { {cb,-sb}, {0.f,0.f}, {0.f,0.f}, {cb,sb} };
        float2 RXc[4] = { {cc,0.f}, {0.f,-sc}, {0.f,-sc}, {cc,0.f} };
        float2 M[4], U[4];
        mm2(RZb, RXa, M);
        mm2(RXc, M, U);
        g_U[t * 4 + 0] = U[0]; g_U[t * 4 + 1] = U[1];
        g_U[t * 4 + 2] = U[2]; g_U[t * 4 + 3] = U[3];
    }

    // Layer-1 ring (8 active wires 0,2,...,14): table bit (7-j) = wire 2j's bit.
    if (t < 512) {
        int d = t >> 8, idx = t & 255;
        float ph = 0.f;
        #pragma unroll
        for (int j = 0; j < 8; j++) {
            int jn = (j + 1) & 7;
            int x = ((idx >> (7 - j)) ^ (idx >> (7 - jn))) & 1;
            ph += (x ? 0.5f : -0.5f) * p1[4 * j + 3 + 32 * d];
        }
        g_t1[t] = make_float2(cosf(ph), sinf(ph));
    }

    // Layer-2 ring (wires 0,4,8,12): table bit (3-j) = wire 4j's bit.
    if (t < 32) {
        int d = t >> 4, idx = t & 15;
        float ph = 0.f;
        #pragma unroll
        for (int j = 0; j < 4; j++) {
            int jn = (j + 1) & 3;
            int x = ((idx >> (3 - j)) ^ (idx >> (3 - jn))) & 1;
            ph += (x ? 0.5f : -0.5f) * p2[4 * j + 3 + 16 * d];
        }
        g_t2[t] = make_float2(cosf(ph), sinf(ph));
    }

    // Layer-3 (wires 0,8): bit1 = wire0, bit0 = wire8. Two RZZ terms on same pair.
    if (t < 8) {
        int d = t >> 2, idx = t & 3;
        int x = ((idx >> 1) ^ idx) & 1;
        float sg = x ? 0.5f : -0.5f;
        float ph = sg * (p3[3 + 8 * d] + p3[7 + 8 * d]);
        g_t3[t] = make_float2(cosf(ph), sinf(ph));
    }

    if (t < 16) out[t] = 0.f;
}

// ---------------------------------------------------------------------------
// Shared helpers. s has 4096 amps; 256 threads; each sweep: 2048 pairs.
// ---------------------------------------------------------------------------
__device__ __forceinline__ void usweep(float2* s, int kb, int uidx) {
    const float2 U0 = g_U[4 * uidx + 0], U1 = g_U[4 * uidx + 1];
    const float2 U2 = g_U[4 * uidx + 2], U3 = g_U[4 * uidx + 3];
    int mask = (1 << kb) - 1;
    int tid = threadIdx.x;
    #pragma unroll
    for (int i = 0; i < 8; i++) {
        int p = tid + i * NT;
        int l0 = ((p & ~mask) << 1) | (p & mask);
        int l1 = l0 | (1 << kb);
        float2 a = s[l0], b = s[l1];
        s[l0] = cadd(cmul(U0, a), cmul(U1, b));
        s[l1] = cadd(cmul(U2, a), cmul(U3, b));
    }
    __syncthreads();
}

// CNOT with local control bit clb and local target bit tb (no internal sync).
__device__ __forceinline__ void cnot_local(float2* s, int clb, int tb) {
    int mask = (1 << tb) - 1;
    int tid = threadIdx.x;
    #pragma unroll
    for (int i = 0; i < 8; i++) {
        int p = tid + i * NT;
        int l0 = ((p & ~mask) << 1) | (p & mask);
        if ((l0 >> clb) & 1) {
            int l1 = l0 | (1 << tb);
            float2 a = s[l0]; s[l0] = s[l1]; s[l1] = a;
        }
    }
}

// Unconditional X on local bit tb (used when CNOT control is a global bit = 1).
__device__ __forceinline__ void flip_bit(float2* s, int tb) {
    int mask = (1 << tb) - 1;
    int tid = threadIdx.x;
    #pragma unroll
    for (int i = 0; i < 8; i++) {
        int p = tid + i * NT;
        int l0 = ((p & ~mask) << 1) | (p & mask);
        int l1 = l0 | (1 << tb);
        float2 a = s[l0]; s[l0] = s[l1]; s[l1] = a;
    }
}

// ---------------------------------------------------------------------------
// Pass 1: local = amp bits 0..11 (wires 4..15). Loads inputs, applies layer0
// depth-0 unitaries on wires 4..15, stores to g_psi. Fully coalesced.
// ---------------------------------------------------------------------------
__global__ __launch_bounds__(NT) void pass1_kernel(
    const float* __restrict__ xre, const float* __restrict__ xim)
{
    __shared__ float2 s[4096];
    int b = blockIdx.x >> 4, tile = blockIdx.x & 15;
    int base = (b << 16) | (tile << 12);
    #pragma unroll
    for (int i = 0; i < 16; i++) {
        int l = threadIdx.x + i * NT;
        s[l] = make_float2(xre[base + l], xim[base + l]);
    }
    __syncthreads();
    for (int w = 4; w < 16; w++) usweep(s, 15 - w, w);   // wire w -> local bit 15-w
    #pragma unroll
    for (int i = 0; i < 16; i++) {
        int l = threadIdx.x + i * NT;
        g_psi[base + l] = s[l];
    }
}

// ---------------------------------------------------------------------------
// Pass 2: local amp bits {0,1,2,3,4,7,9,11,12,13,14,15}  (wires 0-4,6,8,11-15)
// Global amp bits {5,6,8,10} (wires 10,9,7,5).
// Tasks: d0 U on wires 0..3; ring diag D0; d1 U on the 12 local wires.
// ---------------------------------------------------------------------------
__device__ __forceinline__ int expand2(int l) {
    return (l & 0x1F) | ((l & 0x20) << 2) | ((l & 0x40) << 3) | ((l & 0xF80) << 4);
}
__global__ __launch_bounds__(NT) void pass2_kernel() {
    __shared__ float2 s[4096];
    int b = blockIdx.x >> 4, tile = blockIdx.x & 15;
    unsigned tor = ((tile & 3) << 5) | ((tile & 4) << 6) | ((tile & 8) << 7);
    unsigned gb = (unsigned)b << 16;
    #pragma unroll
    for (int i = 0; i < 16; i++) {
        int l = threadIdx.x + i * NT;
        s[l] = g_psi[gb | tor | expand2(l)];
    }
    __syncthreads();
    // layer0 d0 on wires 0..3 (local bits 11,10,9,8; U idx 0..3)
    usweep(s, 11, 0); usweep(s, 10, 1); usweep(s, 9, 2); usweep(s, 8, 3);
    // ring diag depth 0
    #pragma unroll
    for (int i = 0; i < 16; i++) {
        int l = threadIdx.x + i * NT;
        s[l] = cmul(s[l], g_d0[tor | expand2(l)]);
    }
    __syncthreads();
    // layer0 d1 on 12 local wires (U idx = 16 + wire)
    usweep(s, 11, 16); usweep(s, 10, 17); usweep(s, 9, 18); usweep(s, 8, 19);
    usweep(s, 7, 20);  // wire 4
    usweep(s, 6, 22);  // wire 6
    usweep(s, 5, 24);  // wire 8
    usweep(s, 4, 27);  // wire 11
    usweep(s, 3, 28); usweep(s, 2, 29); usweep(s, 1, 30); usweep(s, 0, 31);
    #pragma unroll
    for (int i = 0; i < 16; i++) {
        int l = threadIdx.x + i * NT;
        g_psi[gb | tor | expand2(l)] = s[l];
    }
}

// ---------------------------------------------------------------------------
// Pass 3: local amp bits {0..6,8,10,12,14,15} (wires 0,1,3,5,7,9,10,11,12,13,14,15)
// Global amp bits {7,9,11,13} (wires 8,6,4,2).
// Tasks: d1 U on wires 5,7,9,10; ring diag D1; all 8 pool CNOTs; layer1 d0 U
// on wires 0,10,12,14.
// ---------------------------------------------------------------------------
__device__ __forceinline__ int expand3(int l) {
    return (l & 0x7F) | ((l & 0x80) << 1) | ((l & 0x100) << 2) |
           ((l & 0x200) << 3) | ((l & 0xC00) << 4);
}
__global__ __launch_bounds__(NT) void pass3_kernel() {
    __shared__ float2 s[4096];
    int b = blockIdx.x >> 4, tile = blockIdx.x & 15;
    unsigned tor = ((tile & 1) << 7) | ((tile & 2) << 8) | ((tile & 4) << 9) | ((tile & 8) << 10);
    unsigned gb = (unsigned)b << 16;
    #pragma unroll
    for (int i = 0; i < 16; i++) {
        int l = threadIdx.x + i * NT;
        s[l] = g_psi[gb | tor | expand3(l)];
    }
    __syncthreads();
    // layer0 d1 leftovers: wire5->l8 (U21), wire7->l7 (U23), wire9->l6 (U25), wire10->l5 (U26)
    usweep(s, 8, 21); usweep(s, 7, 23); usweep(s, 6, 25); usweep(s, 5, 26);
    // ring diag depth 1
    #pragma unroll
    for (int i = 0; i < 16; i++) {
        int l = threadIdx.x + i * NT;
        s[l] = cmul(s[l], g_d1[tor | expand3(l)]);
    }
    __syncthreads();
    // pool CNOTs (control wire 2m -> target wire 2m+1):
    cnot_local(s, 11, 10);            __syncthreads();   // (0,1): ctrl local
    if (tile & 8) flip_bit(s, 9);     __syncthreads();   // (2,3): ctrl global (amp bit 13)
    if (tile & 4) flip_bit(s, 8);     __syncthreads();   // (4,5): amp bit 11
    if (tile & 2) flip_bit(s, 7);     __syncthreads();   // (6,7): amp bit 9
    if (tile & 1) flip_bit(s, 6);     __syncthreads();   // (8,9): amp bit 7
    cnot_local(s, 5, 4);              __syncthreads();   // (10,11)
    cnot_local(s, 3, 2);              __syncthreads();   // (12,13)
    cnot_local(s, 1, 0);              __syncthreads();   // (14,15)
    // layer1 d0 U on wires 0,10,12,14 -> locals 11,5,3,1; U idx 32,37,38,39
    usweep(s, 11, 32); usweep(s, 5, 37); usweep(s, 3, 38); usweep(s, 1, 39);
    #pragma unroll
    for (int i = 0; i < 16; i++) {
        int l = threadIdx.x + i * NT;
        g_psi[gb | tor | expand3(l)] = s[l];
    }
}

// ---------------------------------------------------------------------------
// Pass 4: local amp bits {0..7,9,11,13,15} (wires 0,2,4,6,8,9,10,11,12,13,14,15)
// Global amp bits {8,10,12,14} (wires 7,5,3,1).
// Tasks: rest of layer1, layers 2-3 in full, measurement.
// local-bit map for active wires: w0->11, w2->10, w4->9, w6->8, w8->7,
//                                 w10->5, w12->3, w14->1.
// ---------------------------------------------------------------------------
__device__ __forceinline__ int expand4(int l) {
    return (l & 0xFF) | ((l & 0x100) << 1) | ((l & 0x200) << 2) |
           ((l & 0x400) << 3) | ((l & 0x800) << 4);
}
__global__ __launch_bounds__(NT) void pass4_kernel(float* __restrict__ out) {
    __shared__ float2 s[4096];
    __shared__ float ws[8];
    int b = blockIdx.x >> 4, tile = blockIdx.x & 15;
    unsigned tor = ((tile & 1) << 8) | ((tile & 2) << 9) | ((tile & 4) << 10) | ((tile & 8) << 11);
    unsigned gb = (unsigned)b << 16;
    #pragma unroll
    for (int i = 0; i < 16; i++) {
        int l = threadIdx.x + i * NT;
        s[l] = g_psi[gb | tor | expand4(l)];
    }
    __syncthreads();

    // layer1 d0 U on wires 2,4,6,8 -> locals 10,9,8,7; U idx 33..36
    usweep(s, 10, 33); usweep(s, 9, 34); usweep(s, 8, 35); usweep(s, 7, 36);
    // layer1 diag d0: idx8 bit7..0 = local bits 11,10,9,8,7,5,3,1
    #pragma unroll
    for (int i = 0; i < 16; i++) {
        int l = threadIdx.x + i * NT;
        int idx8 = ((l >> 4) & 0xF0) | ((l >> 4) & 8) | ((l >> 3) & 4) | ((l >> 2) & 2) | ((l >> 1) & 1);
        s[l] = cmul(s[l], g_t1[idx8]);
    }
    __syncthreads();
    // layer1 d1 U on all 8 even wires; U idx 40..47
    usweep(s, 11, 40); usweep(s, 10, 41); usweep(s, 9, 42); usweep(s, 8, 43);
    usweep(s, 7, 44);  usweep(s, 5, 45);  usweep(s, 3, 46); usweep(s, 1, 47);
    // layer1 diag d1
    #pragma unroll
    for (int i = 0; i < 16; i++) {
        int l = threadIdx.x + i * NT;
        int idx8 = ((l >> 4) & 0xF0) | ((l >> 4) & 8) | ((l >> 3) & 4) | ((l >> 2) & 2) | ((l >> 1) & 1);
        s[l] = cmul(s[l], g_t1[256 + idx8]);
    }
    __syncthreads();
    // layer1 pool CNOTs: (0->2),(4->6),(8->10),(12->14)
    cnot_local(s, 11, 10); __syncthreads();
    cnot_local(s, 9, 8);   __syncthreads();
    cnot_local(s, 7, 5);   __syncthreads();
    cnot_local(s, 3, 1);   __syncthreads();

    // layer2 d0 U on wires 0,4,8,12 -> locals 11,9,7,3; U idx 48..51
    usweep(s, 11, 48); usweep(s, 9, 49); usweep(s, 7, 50); usweep(s, 3, 51);
    #pragma unroll
    for (int i = 0; i < 16; i++) {
        int l = threadIdx.x + i * NT;
        int idx4 = ((l >> 8) & 8) | ((l >> 7) & 4) | ((l >> 6) & 2) | ((l >> 3) & 1);
        s[l] = cmul(s[l], g_t2[idx4]);
    }
    __syncthreads();
    // layer2 d1 U; U idx 52..55
    usweep(s, 11, 52); usweep(s, 9, 53); usweep(s, 7, 54); usweep(s, 3, 55);
    #pragma unroll
    for (int i = 0; i < 16; i++) {
        int l = threadIdx.x + i * NT;
        int idx4 = ((l >> 8) & 8) | ((l >> 7) & 4) | ((l >> 6) & 2) | ((l >> 3) & 1);
        s[l] = cmul(s[l], g_t2[16 + idx4]);
    }
    __syncthreads();
    // layer2 pool CNOTs: (0->4),(8->12)
    cnot_local(s, 11, 9); __syncthreads();
    cnot_local(s, 7, 3);  __syncthreads();

    // layer3 d0 U on wires 0,8 -> locals 11,7; U idx 56,57
    usweep(s, 11, 56); usweep(s, 7, 57);
    #pragma unroll
    for (int i = 0; i < 16; i++) {
        int l = threadIdx.x + i * NT;
        int idx2 = ((l >> 10) & 2) | ((l >> 7) & 1);
        s[l] = cmul(s[l], g_t3[idx2]);
    }
    __syncthreads();
    // layer3 d1 U; U idx 58,59
    usweep(s, 11, 58); usweep(s, 7, 59);
    #pragma unroll
    for (int i = 0; i < 16; i++) {
        int l = threadIdx.x + i * NT;
        int idx2 = ((l >> 10) & 2) | ((l >> 7) & 1);
        s[l] = cmul(s[l], g_t3[4 + idx2]);
    }
    __syncthreads();
    // layer3 pool CNOT (0->8)
    cnot_local(s, 11, 7); __syncthreads();

    // measure Z on wire 0 (local bit 11): sum (+|a|^2 if bit=0 else -|a|^2)
    float acc = 0.f;
    #pragma unroll
    for (int i = 0; i < 16; i++) {
        int l = threadIdx.x + i * NT;
        float2 a = s[l];
        float p = fmaf(a.x, a.x, a.y * a.y);
        acc += ((l >> 11) & 1) ? -p : p;
    }
    #pragma unroll
    for (int o = 16; o > 0; o >>= 1) acc += __shfl_xor_sync(0xFFFFFFFFu, acc, o);
    if ((threadIdx.x & 31) == 0) ws[threadIdx.x >> 5] = acc;
    __syncthreads();
    if (threadIdx.x == 0) {
        float t = 0.f;
        #pragma unroll
        for (int k = 0; k < 8; k++) t += ws[k];
        atomicAdd(&out[b], t);
    }
}

// ---------------------------------------------------------------------------
extern "C" void kernel_launch(void* const* d_in, const int* in_sizes, int n_in,
                              void* d_out, int out_size) {
    const float* xre = (const float*)d_in[0];
    const float* xim = (const float*)d_in[1];
    const float* p0  = (const float*)d_in[2];
    const float* p1  = (const float*)d_in[3];
    const float* p2  = (const float*)d_in[4];
    const float* p3  = (const float*)d_in[5];
    float* out = (float*)d_out;

    prep_kernel<<<256, NT>>>(p0, p1, p2, p3, out);
    pass1_kernel<<<256, NT>>>(xre, xim);
    pass2_kernel<<<256, NT>>>();
    pass3_kernel<<<256, NT>>>();
    pass4_kernel<<<256, NT>>>(out);
}

// round 8
// speedup vs baseline: 1.3294x; 1.3294x over previous
#include <cuda_runtime.h>

#define NT  256   // prep threads
#define NTP 512   // pass threads

// 8 MB state, tables, composed unitaries — all __device__ globals (no allocs).
__device__ float2 g_psi[16 * 65536];
__device__ float2 g_U[240];       // 60 composed 2x2 unitaries
__device__ float2 g_d0[65536];    // layer0 ring phases, depth 0
__device__ float2 g_d1[65536];    // layer0 ring phases, depth 1
__device__ float2 g_t1[512];      // layer1 ring phases (2 depths x 256)
__device__ float2 g_t2[32];       // layer2 (2 x 16)
__device__ float2 g_t3[8];        // layer3 (2 x 4)

__device__ __forceinline__ float2 cmul(float2 a, float2 b) {
    return make_float2(fmaf(a.x, b.x, -a.y * b.y), fmaf(a.x, b.y, a.y * b.x));
}
__device__ __forceinline__ float2 cadd(float2 a, float2 b) {
    return make_float2(a.x + b.x, a.y + b.y);
}
__device__ __forceinline__ void mm2(const float2* A, const float2* B, float2* C) {
    C[0] = cadd(cmul(A[0], B[0]), cmul(A[1], B[2]));
    C[1] = cadd(cmul(A[0], B[1]), cmul(A[1], B[3]));
    C[2] = cadd(cmul(A[2], B[0]), cmul(A[3], B[2]));
    C[3] = cadd(cmul(A[2], B[1]), cmul(A[3], B[3]));
}

// ---------------------------------------------------------------------------
// Prep: compose RX*RZ*RX unitaries, build all ring-phase tables, zero output.
// ---------------------------------------------------------------------------
__global__ __launch_bounds__(NT) void prep_kernel(
    const float* __restrict__ p0, const float* __restrict__ p1,
    const float* __restrict__ p2, const float* __restrict__ p3,
    float* __restrict__ out)
{
    int t = blockIdx.x * blockDim.x + threadIdx.x;   // 0..65535

    {
        float ph0 = 0.f, ph1 = 0.f;
        #pragma unroll
        for (int j = 0; j < 16; j++) {
            int jn = (j + 1) & 15;
            int x = ((t >> (15 - j)) ^ (t >> (15 - jn))) & 1;
            float sg = x ? 0.5f : -0.5f;
            ph0 += sg * p0[4 * j + 3];
            ph1 += sg * p0[4 * j + 67];
        }
        g_d0[t] = make_float2(cosf(ph0), sinf(ph0));
        g_d1[t] = make_float2(cosf(ph1), sinf(ph1));
    }

    if (t < 60) {
        const float* pp; int base;
        if (t < 32)      { pp = p0; int d = t >> 4;        int s = t & 15;       base = 4 * s + 64 * d; }
        else if (t < 48) { pp = p1; int d = (t - 32) >> 3; int s = (t - 32) & 7; base = 4 * s + 32 * d; }
        else if (t < 56) { pp = p2; int d = (t - 48) >> 2; int s = (t - 48) & 3; base = 4 * s + 16 * d; }
        else             { pp = p3; int d = (t - 56) >> 1; int s = (t - 56) & 1; base = 4 * s + 8 * d; }
        float a = pp[base] * 0.5f, b = pp[base + 1] * 0.5f, c = pp[base + 2] * 0.5f;
        float ca = cosf(a), sa = sinf(a);
        float cb = cosf(b), sb = sinf(b);
        float cc = cosf(c), sc = sinf(c);
        float2 RXa[4] = { {ca,0.f}, {0.f,-sa}, {0.f,-sa}, {ca,0.f} };
        float2 RZb[4] = { {cb,-sb}, {0.f,0.f}, {0.f,0.f}, {cb,sb} };
        float2 RXc[4] = { {cc,0.f}, {0.f,-sc}, {0.f,-sc}, {cc,0.f} };
        float2 M[4], U[4];
        mm2(RZb, RXa, M);
        mm2(RXc, M, U);
        g_U[t * 4 + 0] = U[0]; g_U[t * 4 + 1] = U[1];
        g_U[t * 4 + 2] = U[2]; g_U[t * 4 + 3] = U[3];
    }

    if (t < 512) {
        int d = t >> 8, idx = t & 255;
        float ph = 0.f;
        #pragma unroll
        for (int j = 0; j < 8; j++) {
            int jn = (j + 1) & 7;
            int x = ((idx >> (7 - j)) ^ (idx >> (7 - jn))) & 1;
            ph += (x ? 0.5f : -0.5f) * p1[4 * j + 3 + 32 * d];
        }
        g_t1[t] = make_float2(cosf(ph), sinf(ph));
    }

    if (t < 32) {
        int d = t >> 4, idx = t & 15;
        float ph = 0.f;
        #pragma unroll
        for (int j = 0; j < 4; j++) {
            int jn = (j + 1) & 3;
            int x = ((idx >> (3 - j)) ^ (idx >> (3 - jn))) & 1;
            ph += (x ? 0.5f : -0.5f) * p2[4 * j + 3 + 16 * d];
        }
        g_t2[t] = make_float2(cosf(ph), sinf(ph));
    }

    if (t < 8) {
        int d = t >> 2, idx = t & 3;
        int x = ((idx >> 1) ^ idx) & 1;
        float sg = x ? 0.5f : -0.5f;
        float ph = sg * (p3[3 + 8 * d] + p3[7 + 8 * d]);
        g_t3[t] = make_float2(cosf(ph), sinf(ph));
    }

    if (t < 16) out[t] = 0.f;
}

// ---------------------------------------------------------------------------
// 2-gate cell sweep: apply gate uh on local bit BH and gate ul on local bit BL
// (BH > BL) over the 4096-amp smem tile. 1024 cells / 512 threads = 2 iters.
// Each amp loaded+stored once per sweep; one barrier per sweep.
// Optional phase functor is applied to each amplitude at load time.
// ---------------------------------------------------------------------------
template<int BH, int BL, class PHF>
__device__ __forceinline__ void csweep_ph(float2* s, int uh, int ul, PHF ph) {
    const float2 H0 = g_U[4*uh], H1 = g_U[4*uh+1], H2 = g_U[4*uh+2], H3 = g_U[4*uh+3];
    const float2 L0 = g_U[4*ul], L1 = g_U[4*ul+1], L2 = g_U[4*ul+2], L3 = g_U[4*ul+3];
    #pragma unroll
    for (int it = 0; it < 2; it++) {
        int c = threadIdx.x + it * NTP;
        int y    = ((c >> BL) << (BL + 1)) | (c & ((1 << BL) - 1));
        int base = ((y >> BH) << (BH + 1)) | (y & ((1 << BH) - 1));
        int i01 = base | (1 << BL);
        int i10 = base | (1 << BH);
        int i11 = i10 | (1 << BL);
        float2 a00 = cmul(s[base], ph(base));
        float2 a01 = cmul(s[i01],  ph(i01));
        float2 a10 = cmul(s[i10],  ph(i10));
        float2 a11 = cmul(s[i11],  ph(i11));
        // gate on bit BL: pairs (a00,a01), (a10,a11)
        float2 b00 = cadd(cmul(L0, a00), cmul(L1, a01));
        float2 b10 = cadd(cmul(L0, a10), cmul(L1, a11));
        // gate on bit BH: pairs (b00,b10)
        s[base] = cadd(cmul(H0, b00), cmul(H1, b10));
        s[i10]  = cadd(cmul(H2, b00), cmul(H3, b10));
        float2 b01 = cadd(cmul(L2, a00), cmul(L3, a01));
        float2 b11 = cadd(cmul(L2, a10), cmul(L3, a11));
        s[i01]  = cadd(cmul(H0, b01), cmul(H1, b11));
        s[i11]  = cadd(cmul(H2, b01), cmul(H3, b11));
    }
    __syncthreads();
}

template<int BH, int BL>
__device__ __forceinline__ void csweep(float2* s, int uh, int ul) {
    const float2 H0 = g_U[4*uh], H1 = g_U[4*uh+1], H2 = g_U[4*uh+2], H3 = g_U[4*uh+3];
    const float2 L0 = g_U[4*ul], L1 = g_U[4*ul+1], L2 = g_U[4*ul+2], L3 = g_U[4*ul+3];
    #pragma unroll
    for (int it = 0; it < 2; it++) {
        int c = threadIdx.x + it * NTP;
        int y    = ((c >> BL) << (BL + 1)) | (c & ((1 << BL) - 1));
        int base = ((y >> BH) << (BH + 1)) | (y & ((1 << BH) - 1));
        int i01 = base | (1 << BL);
        int i10 = base | (1 << BH);
        int i11 = i10 | (1 << BL);
        float2 a00 = s[base], a01 = s[i01], a10 = s[i10], a11 = s[i11];
        float2 b00 = cadd(cmul(L0, a00), cmul(L1, a01));
        float2 b10 = cadd(cmul(L0, a10), cmul(L1, a11));
        s[base] = cadd(cmul(H0, b00), cmul(H1, b10));
        s[i10]  = cadd(cmul(H2, b00), cmul(H3, b10));
        float2 b01 = cadd(cmul(L2, a00), cmul(L3, a01));
        float2 b11 = cadd(cmul(L2, a10), cmul(L3, a11));
        s[i01]  = cadd(cmul(H0, b01), cmul(H1, b11));
        s[i11]  = cadd(cmul(H2, b01), cmul(H3, b11));
    }
    __syncthreads();
}

// ---------------------------------------------------------------------------
// Fused diagonal + CNOT-layer permutation. The CNOT layer is an XOR involution
// l -> l ^ f(l), where f depends only on (unchanged) control bits, so orbits
// have size <= 2 and we can swap in place. Applies diag phase FIRST, then perm:
// new[l] = old[p] * ph(p).
// ---------------------------------------------------------------------------
template<class FXF, class PHF>
__device__ __forceinline__ void perm_ph(float2* s, FXF fx, PHF ph) {
    #pragma unroll
    for (int i = 0; i < 8; i++) {
        int l = threadIdx.x + i * NTP;
        int f = fx(l);
        int p = l ^ f;
        if (f == 0) {
            s[l] = cmul(s[l], ph(l));
        } else if (l < p) {
            float2 a = s[l], b = s[p];
            s[l] = cmul(b, ph(p));
            s[p] = cmul(a, ph(l));
        }
    }
    __syncthreads();
}

// ---------------------------------------------------------------------------
// Pass 1: local = amp bits 0..11 (wires 4..15). Layer0 d0 on wires 4..15.
// ---------------------------------------------------------------------------
__global__ __launch_bounds__(NTP, 2) void pass1_kernel(
    const float* __restrict__ xre, const float* __restrict__ xim)
{
    __shared__ float2 s[4096];
    int b = blockIdx.x >> 4, tile = blockIdx.x & 15;
    int base = (b << 16) | (tile << 12);
    #pragma unroll
    for (int i = 0; i < 8; i++) {
        int l = threadIdx.x + i * NTP;
        s[l] = make_float2(xre[base + l], xim[base + l]);
    }
    __syncthreads();
    csweep<11, 0>(s, 4, 15);
    csweep<10, 1>(s, 5, 14);
    csweep<9, 2>(s, 6, 13);
    csweep<8, 3>(s, 7, 12);
    csweep<7, 4>(s, 8, 11);
    csweep<6, 5>(s, 9, 10);
    #pragma unroll
    for (int i = 0; i < 8; i++) {
        int l = threadIdx.x + i * NTP;
        g_psi[base + l] = s[l];
    }
}

// ---------------------------------------------------------------------------
// Pass 2: local amp bits {0-4,7,9,11,12-15}. d0 on wires 0-3; diag D0; d1 on
// 12 local wires. Global amp bits {5,6,8,10}.
// ---------------------------------------------------------------------------
__device__ __forceinline__ int expand2(int l) {
    return (l & 0x1F) | ((l & 0x20) << 2) | ((l & 0x40) << 3) | ((l & 0xF80) << 4);
}
__global__ __launch_bounds__(NTP, 2) void pass2_kernel() {
    __shared__ float2 s[4096];
    int b = blockIdx.x >> 4, tile = blockIdx.x & 15;
    unsigned tor = ((tile & 3) << 5) | ((tile & 4) << 6) | ((tile & 8) << 7);
    unsigned gb = (unsigned)b << 16;
    #pragma unroll
    for (int i = 0; i < 8; i++) {
        int l = threadIdx.x + i * NTP;
        s[l] = g_psi[gb | tor | expand2(l)];
    }
    __syncthreads();
    // layer0 d0 on wires 0..3 (locals 11,10,9,8)
    csweep<11, 8>(s, 0, 3);
    csweep<10, 9>(s, 1, 2);
    // layer0 d1, with ring diag D0 folded into the first sweep's load
    csweep_ph<11, 0>(s, 16, 31, [&](int l) { return g_d0[tor | expand2(l)]; });
    csweep<10, 1>(s, 17, 30);
    csweep<9, 2>(s, 18, 29);
    csweep<8, 3>(s, 19, 28);
    csweep<7, 4>(s, 20, 27);
    csweep<6, 5>(s, 22, 24);
    #pragma unroll
    for (int i = 0; i < 8; i++) {
        int l = threadIdx.x + i * NTP;
        g_psi[gb | tor | expand2(l)] = s[l];
    }
}

// ---------------------------------------------------------------------------
// Pass 3: local amp bits {0-6,8,10,12,14,15}. d1 leftovers (wires 5,7,9,10);
// diag D1 + all 8 pool CNOTs fused; layer1 d0 on wires 0,10,12,14.
// Global amp bits {7,9,11,13} = wires {8,6,4,2}.
// Local map: l11=amp15(w0) l10=amp14(w1) l9=amp12(w3) l8=amp10(w5) l7=amp8(w7)
//            l6=amp6(w9) l5=amp5(w10) l4..l0 = amp4..amp0 (w11..w15)
// ---------------------------------------------------------------------------
__device__ __forceinline__ int expand3(int l) {
    return (l & 0x7F) | ((l & 0x80) << 1) | ((l & 0x100) << 2) |
           ((l & 0x200) << 3) | ((l & 0xC00) << 4);
}
__global__ __launch_bounds__(NTP, 2) void pass3_kernel() {
    __shared__ float2 s[4096];
    int b = blockIdx.x >> 4, tile = blockIdx.x & 15;
    unsigned tor = ((tile & 1) << 7) | ((tile & 2) << 8) | ((tile & 4) << 9) | ((tile & 8) << 10);
    unsigned gb = (unsigned)b << 16;
    #pragma unroll
    for (int i = 0; i < 8; i++) {
        int l = threadIdx.x + i * NTP;
        s[l] = g_psi[gb | tor | expand3(l)];
    }
    __syncthreads();
    // layer0 d1 leftovers: w5->l8(U21), w7->l7(U23), w9->l6(U25), w10->l5(U26)
    csweep<8, 5>(s, 21, 26);
    csweep<7, 6>(s, 23, 25);
    // diag D1 + all 8 pool CNOTs as one fused involution sweep.
    // Targets: l10<-l11, l9<-amp13(tile b3), l8<-amp11(b2), l7<-amp9(b1),
    //          l6<-amp7(b0), l4<-l5, l2<-l3, l0<-l1.
    {
        int fc = (((tile >> 3) & 1) << 9) | (((tile >> 2) & 1) << 8) |
                 (((tile >> 1) & 1) << 7) | ((tile & 1) << 6);
        perm_ph(s,
            [&](int l) {
                return ((((l >> 11) & 1) << 10) | (((l >> 5) & 1) << 4) |
                        (((l >> 3) & 1) << 2) | ((l >> 1) & 1)) | fc;
            },
            [&](int l) { return g_d1[tor | expand3(l)]; });
    }
    // layer1 d0 on wires 0,10,12,14 -> locals 11(U32),5(U37),3(U38),1(U39)
    csweep<11, 1>(s, 32, 39);
    csweep<5, 3>(s, 37, 38);
    #pragma unroll
    for (int i = 0; i < 8; i++) {
        int l = threadIdx.x + i * NTP;
        g_psi[gb | tor | expand3(l)] = s[l];
    }
}

// ---------------------------------------------------------------------------
// Pass 4: local amp bits {0-7,9,11,13,15}. Rest of layer1, layers 2-3, measure.
// Local map: l11=amp15(w0) l10=amp13(w2) l9=amp11(w4) l8=amp9(w6) l7=amp7(w8)
//            l5=amp5(w10) l3=amp3(w12) l1=amp1(w14); l6,l4,l2,l0 spectators.
// ---------------------------------------------------------------------------
__device__ __forceinline__ int expand4(int l) {
    return (l & 0xFF) | ((l & 0x100) << 1) | ((l & 0x200) << 2) |
           ((l & 0x400) << 3) | ((l & 0x800) << 4);
}
__device__ __forceinline__ int p4_idx8(int l) {
    return ((l >> 4) & 0xF8) | ((l >> 3) & 4) | ((l >> 2) & 2) | ((l >> 1) & 1);
}
__device__ __forceinline__ int p4_idx4(int l) {
    return ((l >> 8) & 8) | ((l >> 7) & 4) | ((l >> 6) & 2) | ((l >> 3) & 1);
}
__device__ __forceinline__ int p4_idx2(int l) {
    return ((l >> 10) & 2) | ((l >> 7) & 1);
}
__global__ __launch_bounds__(NTP, 2) void pass4_kernel(float* __restrict__ out) {
    __shared__ float2 s[4096];
    __shared__ float ws[16];
    int b = blockIdx.x >> 4, tile = blockIdx.x & 15;
    unsigned tor = ((tile & 1) << 8) | ((tile & 2) << 9) | ((tile & 4) << 10) | ((tile & 8) << 11);
    unsigned gb = (unsigned)b << 16;
    #pragma unroll
    for (int i = 0; i < 8; i++) {
        int l = threadIdx.x + i * NTP;
        s[l] = g_psi[gb | tor | expand4(l)];
    }
    __syncthreads();

    // layer1 d0 leftovers: w2->l10(U33), w4->l9(U34), w6->l8(U35), w8->l7(U36)
    csweep<10, 7>(s, 33, 36);
    csweep<9, 8>(s, 34, 35);
    // layer1 d1 with diag D0 folded into the first sweep
    csweep_ph<11, 1>(s, 40, 47, [&](int l) { return g_t1[p4_idx8(l)]; });
    csweep<10, 3>(s, 41, 46);
    csweep<9, 5>(s, 42, 45);
    csweep<8, 7>(s, 43, 44);
    // diag D1 + layer1 pool (l10<-l11, l8<-l9, l5<-l7, l1<-l3)
    perm_ph(s,
        [&](int l) {
            return (((l >> 11) & 1) << 10) | (((l >> 9) & 1) << 8) |
                   (((l >> 7) & 1) << 5) | (((l >> 3) & 1) << 1);
        },
        [&](int l) { return g_t1[256 + p4_idx8(l)]; });

    // layer2 d0: w0->l11(U48), w4->l9(U49), w8->l7(U50), w12->l3(U51)
    csweep<11, 3>(s, 48, 51);
    csweep<9, 7>(s, 49, 50);
    // layer2 d1 with diag D0 folded
    csweep_ph<11, 3>(s, 52, 55, [&](int l) { return g_t2[p4_idx4(l)]; });
    csweep<9, 7>(s, 53, 54);
    // diag D1 + layer2 pool (l9<-l11, l3<-l7)
    perm_ph(s,
        [&](int l) {
            return (((l >> 11) & 1) << 9) | (((l >> 7) & 1) << 3);
        },
        [&](int l) { return g_t2[16 + p4_idx4(l)]; });

    // layer3 d0: w0->l11(U56), w8->l7(U57)
    csweep<11, 7>(s, 56, 57);
    // layer3 d1 with diag D0 folded
    csweep_ph<11, 7>(s, 58, 59, [&](int l) { return g_t3[p4_idx2(l)]; });
    // diag D1 + layer3 pool (l7<-l11)
    perm_ph(s,
        [&](int l) { return ((l >> 11) & 1) << 7; },
        [&](int l) { return g_t3[4 + p4_idx2(l)]; });

    // measure Z on wire 0 (local bit 11)
    float acc = 0.f;
    #pragma unroll
    for (int i = 0; i < 8; i++) {
        int l = threadIdx.x + i * NTP;
        float2 a = s[l];
        float p = fmaf(a.x, a.x, a.y * a.y);
        acc += ((l >> 11) & 1) ? -p : p;
    }
    #pragma unroll
    for (int o = 16; o > 0; o >>= 1) acc += __shfl_xor_sync(0xFFFFFFFFu, acc, o);
    if ((threadIdx.x & 31) == 0) ws[threadIdx.x >> 5] = acc;
    __syncthreads();
    if (threadIdx.x == 0) {
        float t = 0.f;
        #pragma unroll
        for (int k = 0; k < 16; k++) t += ws[k];
        atomicAdd(&out[b], t);
    }
}

// ---------------------------------------------------------------------------
extern "C" void kernel_launch(void* const* d_in, const int* in_sizes, int n_in,
                              void* d_out, int out_size) {
    const float* xre = (const float*)d_in[0];
    const float* xim = (const float*)d_in[1];
    const float* p0  = (const float*)d_in[2];
    const float* p1  = (const float*)d_in[3];
    const float* p2  = (const float*)d_in[4];
    const float* p3  = (const float*)d_in[5];
    float* out = (float*)d_out;

    prep_kernel<<<256, NT>>>(p0, p1, p2, p3, out);
    pass1_kernel<<<256, NTP>>>(xre, xim);
    pass2_kernel<<<256, NTP>>>();
    pass3_kernel<<<256, NTP>>>();
    pass4_kernel<<<256, NTP>>>(out);
}